// round 5
// baseline (speedup 1.0000x reference)
#include <cuda_runtime.h>
#include <cuda_bf16.h>
#include <cstdint>

#define B_ 16
#define D_ 128
#define M_ 2048
#define N_ 4096
#define NT 32                 // 128-row tiles per batch
#define CHUNKS 144            // sum_i ceil((32-i)/4)

// Normalized rows scaled by sqrt(2*log2(e)), bf16, [b][n][d] row-major
__device__ __align__(16) __nv_bfloat16 g_zn[(size_t)B_ * N_ * D_];
// Per-row sum(exp2(SC*cos)) and positive d'=SC*cos accumulators
__device__ float g_rowsum[B_ * N_];
__device__ float g_rowpos[B_ * N_];

// ---------------------------------------------------------------- zero scratch
__global__ void zero_kernel(float* out, int n_out) {
    int i = blockIdx.x * blockDim.x + threadIdx.x;
    if (i < B_ * N_) { g_rowsum[i] = 0.f; g_rowpos[i] = 0.f; }
    if (i < n_out) out[i] = 0.f;
}

// ------------------------------------------------------- normalize + transpose
// Scale by sqrt(2*log2 e) so the MMA produces d' = 2*log2(e)*cos directly.
__global__ void normalize_kernel(const float* __restrict__ Zi,
                                 const float* __restrict__ Zj) {
    __shared__ float tile[D_][33];
    __shared__ float part[8][32];
    __shared__ float rnorm_s[32];
    const int m0  = blockIdx.x * 32;
    const int src = blockIdx.y;
    const int b   = blockIdx.z;
    const float* Z = src ? Zj : Zi;
    const int tid = threadIdx.x;
    const int tx = tid & 31, ty = tid >> 5;

    const float* base = Z + (size_t)b * D_ * M_ + m0 + tx;
    float ss = 0.f;
#pragma unroll
    for (int d = ty; d < D_; d += 8) {
        float v = base[(size_t)d * M_];
        tile[d][tx] = v;
        ss += v * v;
    }
    part[ty][tx] = ss;
    __syncthreads();
    if (ty == 0) {
        float s = 0.f;
#pragma unroll
        for (int k = 0; k < 8; k++) s += part[k][tx];
        rnorm_s[tx] = 1.6986437717f / fmaxf(sqrtf(s), 1e-8f);  // sqrt(2*log2 e)
    }
    __syncthreads();

    unsigned* out32 = reinterpret_cast<unsigned*>(g_zn);
    const size_t nbase = (size_t)b * N_ + (size_t)src * M_ + m0;
#pragma unroll
    for (int it = 0; it < 8; it++) {
        int idx = it * 256 + tid;
        int r  = idx >> 6;
        int dp = idx & 63;
        float rn = rnorm_s[r];
        float v0 = tile[2 * dp][r] * rn;
        float v1 = tile[2 * dp + 1][r] * rn;
        __nv_bfloat162 h2 = __floats2bfloat162_rn(v0, v1);
        out32[(nbase + r) * (D_ / 2) + dp] = *reinterpret_cast<unsigned*>(&h2);
    }
}

// ------------------------------------------------------------------- helpers
__device__ __forceinline__ unsigned swz_off(int row, int ch) {
    return (unsigned)(row * 256 + ((ch ^ (row & 7)) << 4));
}
__device__ __forceinline__ void ldsm_x4(unsigned addr, unsigned& r0, unsigned& r1,
                                        unsigned& r2, unsigned& r3) {
    asm volatile("ldmatrix.sync.aligned.m8n8.x4.shared.b16 {%0,%1,%2,%3}, [%4];"
                 : "=r"(r0), "=r"(r1), "=r"(r2), "=r"(r3) : "r"(addr));
}
__device__ __forceinline__ void mma_bf16(float* c, const unsigned* a,
                                         unsigned b0, unsigned b1) {
    asm volatile("mma.sync.aligned.m16n8k16.row.col.f32.bf16.bf16.f32 "
                 "{%0,%1,%2,%3}, {%4,%5,%6,%7}, {%8,%9}, {%0,%1,%2,%3};"
                 : "+f"(c[0]), "+f"(c[1]), "+f"(c[2]), "+f"(c[3])
                 : "r"(a[0]), "r"(a[1]), "r"(a[2]), "r"(a[3]), "r"(b0), "r"(b1));
}
__device__ __forceinline__ float ex2f(float x) {
    float y; asm("ex2.approx.f32 %0, %1;" : "=f"(y) : "f"(x)); return y;
}
__device__ __forceinline__ float lg2f(float x) {
    float y; asm("lg2.approx.f32 %0, %1;" : "=f"(y) : "f"(x)); return y;
}
__device__ __forceinline__ void cp16(unsigned dst, const void* src) {
    asm volatile("cp.async.cg.shared.global [%0], [%1], 16;"
                 :: "r"(dst), "l"(src) : "memory");
}
#define CP_COMMIT() asm volatile("cp.async.commit_group;" ::: "memory")

// 128x64 half-tile MMA: warp covers 32 rows (rowA) x 32 cols (colL within tile).
__device__ __forceinline__ void mma_half(float acc[2][4][4], unsigned sA,
                                         unsigned sBt, int rowA, int colL,
                                         int lane) {
#pragma unroll
    for (int mi = 0; mi < 2; mi++)
#pragma unroll
        for (int ng = 0; ng < 4; ng++)
#pragma unroll
            for (int q = 0; q < 4; q++) acc[mi][ng][q] = 0.f;
#pragma unroll
    for (int k = 0; k < 8; k++) {
        unsigned a[2][4], bb[2][4];
        const int ch = 2 * k + (lane >> 4);
        const int rl = lane & 15;
#pragma unroll
        for (int mi = 0; mi < 2; mi++)
            ldsm_x4(sA + swz_off(rowA + mi * 16 + rl, ch),
                    a[mi][0], a[mi][1], a[mi][2], a[mi][3]);
#pragma unroll
        for (int g = 0; g < 2; g++)
            ldsm_x4(sBt + swz_off(colL + g * 16 + rl, ch),
                    bb[g][0], bb[g][1], bb[g][2], bb[g][3]);
#pragma unroll
        for (int mi = 0; mi < 2; mi++)
#pragma unroll
            for (int ng = 0; ng < 4; ng++)
                mma_bf16(acc[mi][ng], a[mi],
                         bb[ng >> 1][ng & 1], bb[ng >> 1][(ng & 1) + 2]);
    }
}

// Epilogue for one 128x64 half: exp2, row partials (regs), col sums (global REDG).
// colG = half*64 + wc32 (tile-local col base of this warp's 32 cols).
__device__ __forceinline__ void epi_half(float acc[2][4][4], float rs[4],
                                         float* rowsum_b, float* rowpos_b,
                                         float* apos, int j, int ti, int rowA,
                                         int colG, int lane, bool dt, bool pt) {
    if (!dt && !pt) {
#pragma unroll
        for (int mi = 0; mi < 2; mi++)
#pragma unroll
            for (int ng = 0; ng < 4; ng++)
#pragma unroll
                for (int q = 0; q < 4; q++) {
                    float e = ex2f(acc[mi][ng][q]);
                    acc[mi][ng][q] = e;
                    rs[mi * 2 + (q >> 1)] += e;
                }
    } else {
#pragma unroll
        for (int mi = 0; mi < 2; mi++)
#pragma unroll
            for (int ng = 0; ng < 4; ng++)
#pragma unroll
                for (int q = 0; q < 4; q++) {
                    const int lr = rowA + mi * 16 + (q >> 1) * 8 + (lane >> 2);
                    const int gc = colG + ng * 8 + ((lane & 3) << 1) + (q & 1);
                    const float dv = acc[mi][ng][q];
                    if (pt && lr == gc) {
                        atomicAdd(&apos[lr], dv);
                        atomicAdd(&rowpos_b[j * 128 + lr], dv);
                    }
                    float e = (dt && lr == gc) ? 0.f : ex2f(dv);
                    acc[mi][ng][q] = e;
                    rs[mi * 2 + (q >> 1)] += e;
                }
    }
    if (!dt) {
#pragma unroll
        for (int ng = 0; ng < 4; ng++)
#pragma unroll
            for (int ql = 0; ql < 2; ql++) {
                float cs = (acc[0][ng][ql] + acc[0][ng][ql + 2])
                         + (acc[1][ng][ql] + acc[1][ng][ql + 2]);
                cs += __shfl_xor_sync(0xffffffffu, cs, 4);
                cs += __shfl_xor_sync(0xffffffffu, cs, 8);
                cs += __shfl_xor_sync(0xffffffffu, cs, 16);
                if (lane < 4)
                    atomicAdd(&rowsum_b[j * 128 + colG + ng * 8 + lane * 2 + ql], cs);
            }
    }
}

// ------------------------------------------------------------------ main pass
// One CTA per (row-tile i, chunk of up to 4 col-tiles). A resident, B depth-2.
// Each tile split into two 128x64 halves; skewed MMA/epilogue pipeline:
//   MMA(h0,t) || EPI(h1,t-1);  MMA(h1,t) || EPI(h0,t)
__global__ __launch_bounds__(256, 2) void simclr_chunk_kernel() {
    extern __shared__ char smem[];          // A 32K | B0 32K | B1 32K
    __shared__ float asum[128], apos[128];

    const int b = blockIdx.y;
    int rem = blockIdx.x, ti = 0;
    for (;;) { int c = (NT - ti + 3) >> 2; if (rem < c) break; rem -= c; ti++; }
    const int j0 = ti + rem * 4;
    const int nt = min(4, NT - j0);

    const int tid = threadIdx.x;
    const int lane = tid & 31, w = tid >> 5;
    const int rowA = (w >> 1) * 32;
    const int wc32 = (w & 1) * 32;

    unsigned sA = (unsigned)__cvta_generic_to_shared(smem);
    unsigned sB[2] = {sA + 32768, sA + 65536};

    if (tid < 128) { asum[tid] = 0.f; apos[tid] = 0.f; }

    const char* zb = (const char*)(g_zn + (size_t)b * N_ * D_);
    const char* Ag = zb + (size_t)ti * 128 * 256;
#pragma unroll
    for (int it = 0; it < 8; it++) {
        int idx = it * 256 + tid;
        int row = idx >> 4, ch = idx & 15;
        cp16(sA + swz_off(row, ch), Ag + row * 256 + ch * 16);
        cp16(sB[0] + swz_off(row, ch),
             zb + (size_t)j0 * 128 * 256 + row * 256 + ch * 16);
    }
    CP_COMMIT();
    if (nt > 1) {
        const char* Bg = zb + (size_t)(j0 + 1) * 128 * 256;
#pragma unroll
        for (int it = 0; it < 8; it++) {
            int idx = it * 256 + tid;
            int row = idx >> 4, ch = idx & 15;
            cp16(sB[1] + swz_off(row, ch), Bg + row * 256 + ch * 16);
        }
    }
    CP_COMMIT();

    float rs[4] = {0.f, 0.f, 0.f, 0.f};
    float acc0[2][4][4], acc1[2][4][4];
    float* rowsum_b = g_rowsum + b * N_;
    float* rowpos_b = g_rowpos + b * N_;

    for (int t = 0; t < nt; t++) {
        asm volatile("cp.async.wait_group 1;" ::: "memory");
        __syncthreads();

        const int j = j0 + t;
        const unsigned sBt = sB[t & 1];
        const bool dt = (j == ti);
        const bool pt = (j == ti + 16);

        // MMA half 0 (tensor) overlaps EPI of previous tile's half 1 (MUFU)
        mma_half(acc0, sA, sBt, rowA, wc32, lane);
        if (t > 0) {
            const int jp = j - 1;
            epi_half(acc1, rs, rowsum_b, rowpos_b, apos, jp, ti, rowA,
                     64 + wc32, lane, jp == ti, jp == ti + 16);
        }
        // MMA half 1 overlaps prefetch + EPI half 0
        mma_half(acc1, sA, sBt, rowA, 64 + wc32, lane);
        if (t + 2 < nt) {
            const char* Bg = zb + (size_t)(j + 2) * 128 * 256;
            unsigned dst = sB[t & 1];
#pragma unroll
            for (int it = 0; it < 8; it++) {
                int idx = it * 256 + tid;
                int row = idx >> 4, ch = idx & 15;
                cp16(dst + swz_off(row, ch), Bg + row * 256 + ch * 16);
            }
        }
        CP_COMMIT();
        epi_half(acc0, rs, rowsum_b, rowpos_b, apos, j, ti, rowA,
                 wc32, lane, dt, pt);
    }
    // flush: EPI of last tile's half 1
    {
        const int j = j0 + nt - 1;
        epi_half(acc1, rs, rowsum_b, rowpos_b, apos, j, ti, rowA,
                 64 + wc32, lane, j == ti, j == ti + 16);
    }

    // CTA-end: quad-reduce row partials, combine, push rows of tile ti
#pragma unroll
    for (int idx = 0; idx < 4; idx++) {
        rs[idx] += __shfl_xor_sync(0xffffffffu, rs[idx], 1);
        rs[idx] += __shfl_xor_sync(0xffffffffu, rs[idx], 2);
    }
    if ((lane & 3) == 0) {
#pragma unroll
        for (int idx = 0; idx < 4; idx++)
            atomicAdd(&asum[rowA + (idx >> 1) * 16 + (idx & 1) * 8 + (lane >> 2)],
                      rs[idx]);
    }
    __syncthreads();
    const bool had_pt = (ti + 16 >= j0) && (ti + 16 < j0 + nt);
    if (tid < 128) {
        atomicAdd(&rowsum_b[ti * 128 + tid], asum[tid]);
        if (had_pt) atomicAdd(&rowpos_b[ti * 128 + tid], apos[tid]);
    }
}

// -------------------------------------------------------------------- finalize
// loss_row = ln(sum e^{2cos}) - 2cos_pos = ln2 * (log2(rowsum) - rowpos)
__global__ void finalize_kernel(float* __restrict__ out) {
    const int r = blockIdx.x * 256 + threadIdx.x;
    float v = 0.6931471805599453f * (lg2f(g_rowsum[r]) - g_rowpos[r]);
#pragma unroll
    for (int o = 16; o > 0; o >>= 1) v += __shfl_xor_sync(0xffffffffu, v, o);
    __shared__ float red[8];
    const int w = threadIdx.x >> 5;
    if ((threadIdx.x & 31) == 0) red[w] = v;
    __syncthreads();
    if (threadIdx.x == 0) {
        float s = 0.f;
#pragma unroll
        for (int k = 0; k < 8; k++) s += red[k];
        atomicAdd(out, s * (1.f / ((float)B_ * (float)N_)));
    }
}

// ----------------------------------------------------------------- entry point
extern "C" void kernel_launch(void* const* d_in, const int* in_sizes, int n_in,
                              void* d_out, int out_size) {
    const float* Zi = (const float*)d_in[0];
    const float* Zj = (const float*)d_in[1];
    float* out = (float*)d_out;
    (void)in_sizes; (void)n_in;

    cudaFuncSetAttribute(simclr_chunk_kernel,
                         cudaFuncAttributeMaxDynamicSharedMemorySize, 98304);

    zero_kernel<<<(B_ * N_ + 255) / 256, 256>>>(out, out_size);
    normalize_kernel<<<dim3(M_ / 32, 2, B_), 256>>>(Zi, Zj);
    simclr_chunk_kernel<<<dim3(CHUNKS, B_), 256, 98304>>>();
    finalize_kernel<<<B_ * N_ / 256, 256>>>(out);
}